// round 2
// baseline (speedup 1.0000x reference)
#include <cuda_runtime.h>
#include <cuda_bf16.h>

#define NN   50000
#define EE   800000
#define HH   256
#define GG   64
#define OUTD 24

// Scratch (allocation-free rule: __device__ globals)
__device__ float g_bufA[NN * HH];
__device__ float g_bufB[NN * HH];
__device__ float g_agg [NN * HH];
__device__ float g_pooled[GG * HH];
__device__ float g_cnt[GG];

__device__ __forceinline__ void atomAdd4(float* a, float4 v) {
    asm volatile("red.global.add.v4.f32 [%0], {%1,%2,%3,%4};"
                 :: "l"(a), "f"(v.x), "f"(v.y), "f"(v.z), "f"(v.w) : "memory");
}

__global__ void zero_kernel(float* __restrict__ p, int n) {
    int i = blockIdx.x * blockDim.x + threadIdx.x;
    if (i < n) p[i] = 0.f;
}

// ---------------- layer 1 (F_IN = 3) ----------------
__global__ void scatter3_kernel(const float* __restrict__ x,
                                const int* __restrict__ src,
                                const int* __restrict__ dst,
                                float* __restrict__ agg3) {
    int e = blockIdx.x * blockDim.x + threadIdx.x;
    if (e >= EE) return;
    int s = src[e], d = dst[e];
    atomicAdd(&agg3[d * 3 + 0], x[s * 3 + 0]);
    atomicAdd(&agg3[d * 3 + 1], x[s * 3 + 1]);
    atomicAdd(&agg3[d * 3 + 2], x[s * 3 + 2]);
}

__global__ void layer1_kernel(const float* __restrict__ x,
                              const float* __restrict__ agg3,
                              const float* __restrict__ wr,   // [3,256]
                              const float* __restrict__ wo,   // [3,256]
                              const float* __restrict__ bias, // [256]
                              float* __restrict__ out) {
    __shared__ float swr[3 * HH];
    __shared__ float swo[3 * HH];
    int tid = threadIdx.x;
    for (int i = tid; i < 3 * HH; i += 256) { swr[i] = wr[i]; swo[i] = wo[i]; }
    __syncthreads();
    float bb = bias[tid];
    int base = blockIdx.x * 16;
    for (int nn = 0; nn < 16; ++nn) {
        int node = base + nn;
        if (node >= NN) break;
        float a0 = agg3[node * 3 + 0], a1 = agg3[node * 3 + 1], a2 = agg3[node * 3 + 2];
        float x0 = x[node * 3 + 0],    x1 = x[node * 3 + 1],    x2 = x[node * 3 + 2];
        float v = a0 * swr[0 * HH + tid] + a1 * swr[1 * HH + tid] + a2 * swr[2 * HH + tid]
                + x0 * swo[0 * HH + tid] + x1 * swo[1 * HH + tid] + x2 * swo[2 * HH + tid]
                + bb;
        out[node * HH + tid] = fmaxf(v, 0.f);
    }
}

// ---------------- edge aggregation (H = 256) ----------------
// thread -> (edge, 16B column chunk). Warp covers 32 consecutive chunks of
// one edge (64 chunks/edge, blockDim % 64 == 0) so src/dst loads broadcast
// and the 1KB row gather/atomic is fully coalesced.
__global__ void scatter_kernel(const float* __restrict__ h,
                               const int* __restrict__ src,
                               const int* __restrict__ dst,
                               float* __restrict__ agg) {
    int idx = blockIdx.x * blockDim.x + threadIdx.x;
    int e = idx >> 6;
    int q = (idx & 63) << 2;
    int s = src[e], d = dst[e];
    float4 v = *(const float4*)&h[(size_t)s * HH + q];
    atomAdd4(&agg[(size_t)d * HH + q], v);
}

// ---------------- dual GEMM + bias + relu ----------------
// out = relu(A1 @ W1 + A2 @ W2 + bias), A: [N,256], W: [256,256]
// Tile 128x128, K-tile 8, 256 threads, 8x8 accum per thread.
__global__ __launch_bounds__(256, 2)
void gemm_dual_relu(const float* __restrict__ A1,
                    const float* __restrict__ A2,
                    const float* __restrict__ W1,
                    const float* __restrict__ W2,
                    const float* __restrict__ bias,
                    float* __restrict__ out) {
    __shared__ float As[8][128];
    __shared__ float Bs[8][128];

    int tid = threadIdx.x;
    int m0 = blockIdx.x * 128;
    int n0 = blockIdx.y * 128;
    int tm = (tid / 16) * 8;
    int tn = (tid % 16) * 8;

    int la_row = tid >> 1;          // 0..127
    int la_col = (tid & 1) * 4;     // 0 or 4
    int lb_k   = tid >> 5;          // 0..7
    int lb_n   = (tid & 31) * 4;    // 0..124

    float acc[8][8];
    #pragma unroll
    for (int i = 0; i < 8; i++)
        #pragma unroll
        for (int j = 0; j < 8; j++) acc[i][j] = 0.f;

    int gr = m0 + la_row;
    if (gr >= NN) gr = NN - 1;      // clamp; junk rows never stored

    for (int phase = 0; phase < 2; ++phase) {
        const float* A = phase ? A2 : A1;
        const float* W = phase ? W2 : W1;
        for (int k0 = 0; k0 < HH; k0 += 8) {
            __syncthreads();
            float4 a = *(const float4*)&A[(size_t)gr * HH + k0 + la_col];
            As[la_col + 0][la_row] = a.x;
            As[la_col + 1][la_row] = a.y;
            As[la_col + 2][la_row] = a.z;
            As[la_col + 3][la_row] = a.w;
            *(float4*)&Bs[lb_k][lb_n] =
                *(const float4*)&W[(size_t)(k0 + lb_k) * HH + n0 + lb_n];
            __syncthreads();
            #pragma unroll
            for (int k = 0; k < 8; ++k) {
                float a0[8], b0[8];
                *(float4*)&a0[0] = *(float4*)&As[k][tm];
                *(float4*)&a0[4] = *(float4*)&As[k][tm + 4];
                *(float4*)&b0[0] = *(float4*)&Bs[k][tn];
                *(float4*)&b0[4] = *(float4*)&Bs[k][tn + 4];
                #pragma unroll
                for (int i = 0; i < 8; i++)
                    #pragma unroll
                    for (int j = 0; j < 8; j++)
                        acc[i][j] += a0[i] * b0[j];
            }
        }
    }

    #pragma unroll
    for (int i = 0; i < 8; i++) {
        int r = m0 + tm + i;
        if (r >= NN) break;
        #pragma unroll
        for (int j = 0; j < 8; j += 4) {
            float4 v;
            v.x = fmaxf(acc[i][j + 0] + bias[n0 + tn + j + 0], 0.f);
            v.y = fmaxf(acc[i][j + 1] + bias[n0 + tn + j + 1], 0.f);
            v.z = fmaxf(acc[i][j + 2] + bias[n0 + tn + j + 2], 0.f);
            v.w = fmaxf(acc[i][j + 3] + bias[n0 + tn + j + 3], 0.f);
            *(float4*)&out[(size_t)r * HH + n0 + tn + j] = v;
        }
    }
}

// ---------------- pooling + head ----------------
__global__ void pool_kernel(const float* __restrict__ h,
                            const int* __restrict__ batch,
                            float* __restrict__ pooled,
                            float* __restrict__ cnt) {
    int idx = blockIdx.x * blockDim.x + threadIdx.x;
    if (idx >= NN * 64) return;
    int i = idx >> 6;
    int q = (idx & 63) << 2;
    int b = batch[i];
    float4 v = *(const float4*)&h[(size_t)i * HH + q];
    atomAdd4(&pooled[(size_t)b * HH + q], v);
    if ((idx & 63) == 0) atomicAdd(&cnt[b], 1.f);
}

__global__ void head_kernel(const float* __restrict__ pooled,
                            const float* __restrict__ cnt,
                            const float* __restrict__ w_out,  // [256,24]
                            const float* __restrict__ b_out,  // [24]
                            float* __restrict__ out) {
    __shared__ float row[HH];
    int g = blockIdx.x, t = threadIdx.x;
    float c = fmaxf(cnt[g], 1.f);
    row[t] = pooled[g * HH + t] / c;
    __syncthreads();
    if (t < OUTD) {
        float s = b_out[t];
        #pragma unroll 8
        for (int k = 0; k < HH; k++) s += row[k] * w_out[k * OUTD + t];
        out[g * OUTD + t] = s;
    }
}

extern "C" void kernel_launch(void* const* d_in, const int* in_sizes, int n_in,
                              void* d_out, int out_size) {
    const float* x       = (const float*)d_in[0];
    const int*   ei      = (const int*)  d_in[1];
    const int*   batch   = (const int*)  d_in[2];
    const float* w_rel1  = (const float*)d_in[3];
    const float* w_root1 = (const float*)d_in[4];
    const float* b1      = (const float*)d_in[5];
    const float* w_rel   = (const float*)d_in[6];
    const float* w_root  = (const float*)d_in[7];
    const float* b       = (const float*)d_in[8];
    const float* w_out   = (const float*)d_in[9];
    const float* b_out   = (const float*)d_in[10];
    float* out = (float*)d_out;

    const int* src = ei;
    const int* dst = ei + EE;

    float *bufA, *bufB, *agg, *pooled, *cnt;
    cudaGetSymbolAddress((void**)&bufA,   g_bufA);
    cudaGetSymbolAddress((void**)&bufB,   g_bufB);
    cudaGetSymbolAddress((void**)&agg,    g_agg);
    cudaGetSymbolAddress((void**)&pooled, g_pooled);
    cudaGetSymbolAddress((void**)&cnt,    g_cnt);

    // ---- layer 1 (F_IN=3) ----
    zero_kernel<<<(NN * 3 + 255) / 256, 256>>>(agg, NN * 3);
    scatter3_kernel<<<(EE + 255) / 256, 256>>>(x, src, dst, agg);
    layer1_kernel<<<(NN + 15) / 16, 256>>>(x, agg, w_rel1, w_root1, b1, bufA);

    // ---- layers 2..7 ----
    float* cur = bufA;
    float* nxt = bufB;
    const int zgrid = (NN * HH + 255) / 256;
    dim3 ggrid((NN + 127) / 128, HH / 128);
    for (int l = 0; l < 6; ++l) {
        zero_kernel<<<zgrid, 256>>>(agg, NN * HH);
        scatter_kernel<<<(EE * 64) / 256, 256>>>(cur, src, dst, agg);
        gemm_dual_relu<<<ggrid, 256>>>(agg, cur,
                                       w_rel  + (size_t)l * HH * HH,
                                       w_root + (size_t)l * HH * HH,
                                       b + (size_t)l * HH, nxt);
        float* t = cur; cur = nxt; nxt = t;
    }

    // ---- pool + head ----
    zero_kernel<<<(GG * HH + 255) / 256, 256>>>(pooled, GG * HH);
    zero_kernel<<<1, 64>>>(cnt, GG);
    pool_kernel<<<(NN * 64 + 255) / 256, 256>>>(cur, batch, pooled, cnt);
    head_kernel<<<GG, 256>>>(pooled, cnt, w_out, b_out, out);
}

// round 3
// speedup vs baseline: 1.2825x; 1.2825x over previous
#include <cuda_runtime.h>
#include <cuda_bf16.h>

#define NN   50000
#define EE   800000
#define HH   256
#define GG   64
#define OUTD 24

// Scratch (allocation-free rule: __device__ globals)
__device__ float g_bufA[NN * HH];
__device__ float g_bufB[NN * HH];
__device__ float g_agg [NN * HH];
__device__ float g_pooled[GG * HH];
__device__ float g_cnt[GG];
__device__ int   g_deg[NN];
__device__ int   g_pos[NN];
__device__ int   g_rowptr[NN + 1];
__device__ int   g_csr_src[EE];

// ---- f32x2 packed-FMA helpers (sm_103a FFMA2, PTX-only) ----
typedef unsigned long long ull;
__device__ __forceinline__ ull pack2(float x) {
    ull r; asm("mov.b64 %0, {%1, %1};" : "=l"(r) : "f"(x)); return r;
}
__device__ __forceinline__ void fma2(ull& d, ull a, ull b) {
    asm("fma.rn.f32x2 %0, %1, %2, %0;" : "+l"(d) : "l"(a), "l"(b));
}
__device__ __forceinline__ float2 unpack2(ull v) {
    float2 f; asm("mov.b64 {%0, %1}, %2;" : "=f"(f.x), "=f"(f.y) : "l"(v)); return f;
}

__device__ __forceinline__ void atomAdd4(float* a, float4 v) {
    asm volatile("red.global.add.v4.f32 [%0], {%1,%2,%3,%4};"
                 :: "l"(a), "f"(v.x), "f"(v.y), "f"(v.z), "f"(v.w) : "memory");
}

__global__ void zero_kernel(float* __restrict__ p, int n) {
    int i = blockIdx.x * blockDim.x + threadIdx.x;
    if (i < n) p[i] = 0.f;
}

// ---------------- CSR build (once per launch) ----------------
__global__ void hist_kernel(const int* __restrict__ dst, int* __restrict__ deg) {
    int e = blockIdx.x * blockDim.x + threadIdx.x;
    if (e < EE) atomicAdd(&deg[dst[e]], 1);
}

// single-block exclusive scan of deg -> rowptr (and pos copy)
__global__ void scan_kernel(const int* __restrict__ deg,
                            int* __restrict__ rowptr,
                            int* __restrict__ pos) {
    const int T = 1024;
    const int CH = (NN + T - 1) / T;   // 49
    __shared__ int wsum[32];
    int t = threadIdx.x;
    int start = t * CH;
    int end   = min(start + CH, NN);
    int s = 0;
    for (int i = start; i < end; ++i) s += deg[i];
    // warp inclusive scan
    int lane = t & 31, wid = t >> 5;
    int v = s;
    #pragma unroll
    for (int o = 1; o < 32; o <<= 1) {
        int u = __shfl_up_sync(0xffffffff, v, o);
        if (lane >= o) v += u;
    }
    if (lane == 31) wsum[wid] = v;
    __syncthreads();
    if (wid == 0) {
        int w = (lane < 32) ? wsum[lane] : 0;
        #pragma unroll
        for (int o = 1; o < 32; o <<= 1) {
            int u = __shfl_up_sync(0xffffffff, w, o);
            if (lane >= o) w += u;
        }
        wsum[lane] = w;
    }
    __syncthreads();
    int excl = v - s + (wid ? wsum[wid - 1] : 0);  // exclusive prefix for this thread
    int base = excl;
    for (int i = start; i < end; ++i) {
        rowptr[i] = base;
        pos[i]    = base;
        base += deg[i];
    }
    if (t == 0) rowptr[NN] = EE;
}

__global__ void fill_kernel(const int* __restrict__ src,
                            const int* __restrict__ dst,
                            int* __restrict__ pos,
                            int* __restrict__ csr_src) {
    int e = blockIdx.x * blockDim.x + threadIdx.x;
    if (e >= EE) return;
    int p = atomicAdd(&pos[dst[e]], 1);
    csr_src[p] = src[e];
}

// ---------------- layer 1 (F_IN = 3) ----------------
__global__ void scatter3_kernel(const float* __restrict__ x,
                                const int* __restrict__ src,
                                const int* __restrict__ dst,
                                float* __restrict__ agg3) {
    int e = blockIdx.x * blockDim.x + threadIdx.x;
    if (e >= EE) return;
    int s = src[e], d = dst[e];
    atomicAdd(&agg3[d * 3 + 0], x[s * 3 + 0]);
    atomicAdd(&agg3[d * 3 + 1], x[s * 3 + 1]);
    atomicAdd(&agg3[d * 3 + 2], x[s * 3 + 2]);
}

__global__ void layer1_kernel(const float* __restrict__ x,
                              const float* __restrict__ agg3,
                              const float* __restrict__ wr,
                              const float* __restrict__ wo,
                              const float* __restrict__ bias,
                              float* __restrict__ out) {
    __shared__ float swr[3 * HH];
    __shared__ float swo[3 * HH];
    int tid = threadIdx.x;
    for (int i = tid; i < 3 * HH; i += 256) { swr[i] = wr[i]; swo[i] = wo[i]; }
    __syncthreads();
    float bb = bias[tid];
    int base = blockIdx.x * 16;
    for (int nn = 0; nn < 16; ++nn) {
        int node = base + nn;
        if (node >= NN) break;
        float a0 = agg3[node * 3 + 0], a1 = agg3[node * 3 + 1], a2 = agg3[node * 3 + 2];
        float x0 = x[node * 3 + 0],    x1 = x[node * 3 + 1],    x2 = x[node * 3 + 2];
        float v = a0 * swr[0 * HH + tid] + a1 * swr[1 * HH + tid] + a2 * swr[2 * HH + tid]
                + x0 * swo[0 * HH + tid] + x1 * swo[1 * HH + tid] + x2 * swo[2 * HH + tid]
                + bb;
        out[node * HH + tid] = fmaxf(v, 0.f);
    }
}

// ---------------- CSR gather aggregation (H = 256) ----------------
// 2 warps per node, each warp covers 128 cols (lane*4 float4).
__global__ void gather_kernel(const float* __restrict__ h,
                              const int* __restrict__ rowptr,
                              const int* __restrict__ csr_src,
                              float* __restrict__ agg) {
    int w = (blockIdx.x * blockDim.x + threadIdx.x) >> 5;
    int lane = threadIdx.x & 31;
    int node = w >> 1;
    if (node >= NN) return;
    int col = ((w & 1) << 7) + (lane << 2);
    int e0 = rowptr[node];
    int e1 = rowptr[node + 1];
    float4 acc = make_float4(0.f, 0.f, 0.f, 0.f);
    for (int e = e0; e < e1; ++e) {
        int s = __ldg(&csr_src[e]);
        float4 v = *(const float4*)&h[(size_t)s * HH + col];
        acc.x += v.x; acc.y += v.y; acc.z += v.z; acc.w += v.w;
    }
    *(float4*)&agg[(size_t)node * HH + col] = acc;
}

// ---------------- dual GEMM + bias + relu (FFMA2) ----------------
// out = relu(A1 @ W1 + A2 @ W2 + bias). Tile 128x128xK8, 256 thr, 8x8/thread,
// accumulators held as packed f32x2 (4 ull per output row-octet).
__global__ __launch_bounds__(256, 2)
void gemm_dual_relu(const float* __restrict__ A1,
                    const float* __restrict__ A2,
                    const float* __restrict__ W1,
                    const float* __restrict__ W2,
                    const float* __restrict__ bias,
                    float* __restrict__ out) {
    __shared__ float As[8][128];
    __shared__ float Bs[8][128];

    int tid = threadIdx.x;
    int m0 = blockIdx.x * 128;
    int n0 = blockIdx.y * 128;
    int tm = (tid / 16) * 8;
    int tn = (tid % 16) * 8;

    int la_row = tid >> 1;
    int la_col = (tid & 1) * 4;
    int lb_k   = tid >> 5;
    int lb_n   = (tid & 31) * 4;

    ull accp[8][4];
    #pragma unroll
    for (int i = 0; i < 8; i++)
        #pragma unroll
        for (int j = 0; j < 4; j++) accp[i][j] = 0ULL;

    int gr = m0 + la_row;
    if (gr >= NN) gr = NN - 1;      // clamp; junk rows never stored

    for (int phase = 0; phase < 2; ++phase) {
        const float* A = phase ? A2 : A1;
        const float* W = phase ? W2 : W1;
        for (int k0 = 0; k0 < HH; k0 += 8) {
            __syncthreads();
            float4 a = *(const float4*)&A[(size_t)gr * HH + k0 + la_col];
            As[la_col + 0][la_row] = a.x;
            As[la_col + 1][la_row] = a.y;
            As[la_col + 2][la_row] = a.z;
            As[la_col + 3][la_row] = a.w;
            *(float4*)&Bs[lb_k][lb_n] =
                *(const float4*)&W[(size_t)(k0 + lb_k) * HH + n0 + lb_n];
            __syncthreads();
            #pragma unroll
            for (int k = 0; k < 8; ++k) {
                float a0[8];
                *(float4*)&a0[0] = *(float4*)&As[k][tm];
                *(float4*)&a0[4] = *(float4*)&As[k][tm + 4];
                const ull* bp = (const ull*)&Bs[k][tn];
                ull b2[4];
                #pragma unroll
                for (int j = 0; j < 4; j++) b2[j] = bp[j];
                #pragma unroll
                for (int i = 0; i < 8; i++) {
                    ull ap = pack2(a0[i]);
                    #pragma unroll
                    for (int j = 0; j < 4; j++) fma2(accp[i][j], ap, b2[j]);
                }
            }
        }
    }

    float bb[8];
    #pragma unroll
    for (int j = 0; j < 8; j++) bb[j] = bias[n0 + tn + j];

    #pragma unroll
    for (int i = 0; i < 8; i++) {
        int r = m0 + tm + i;
        if (r >= NN) break;
        float v[8];
        #pragma unroll
        for (int j = 0; j < 4; j++) {
            float2 f = unpack2(accp[i][j]);
            v[2 * j + 0] = fmaxf(f.x + bb[2 * j + 0], 0.f);
            v[2 * j + 1] = fmaxf(f.y + bb[2 * j + 1], 0.f);
        }
        *(float4*)&out[(size_t)r * HH + tn + n0 + 0] = *(float4*)&v[0];
        *(float4*)&out[(size_t)r * HH + tn + n0 + 4] = *(float4*)&v[4];
    }
}

// ---------------- pooling + head ----------------
__global__ void pool_kernel(const float* __restrict__ h,
                            const int* __restrict__ batch,
                            float* __restrict__ pooled,
                            float* __restrict__ cnt) {
    int idx = blockIdx.x * blockDim.x + threadIdx.x;
    if (idx >= NN * 64) return;
    int i = idx >> 6;
    int q = (idx & 63) << 2;
    int b = batch[i];
    float4 v = *(const float4*)&h[(size_t)i * HH + q];
    atomAdd4(&pooled[(size_t)b * HH + q], v);
    if ((idx & 63) == 0) atomicAdd(&cnt[b], 1.f);
}

__global__ void head_kernel(const float* __restrict__ pooled,
                            const float* __restrict__ cnt,
                            const float* __restrict__ w_out,
                            const float* __restrict__ b_out,
                            float* __restrict__ out) {
    __shared__ float row[HH];
    int g = blockIdx.x, t = threadIdx.x;
    float c = fmaxf(cnt[g], 1.f);
    row[t] = pooled[g * HH + t] / c;
    __syncthreads();
    if (t < OUTD) {
        float s = b_out[t];
        #pragma unroll 8
        for (int k = 0; k < HH; k++) s += row[k] * w_out[k * OUTD + t];
        out[g * OUTD + t] = s;
    }
}

extern "C" void kernel_launch(void* const* d_in, const int* in_sizes, int n_in,
                              void* d_out, int out_size) {
    const float* x       = (const float*)d_in[0];
    const int*   ei      = (const int*)  d_in[1];
    const int*   batch   = (const int*)  d_in[2];
    const float* w_rel1  = (const float*)d_in[3];
    const float* w_root1 = (const float*)d_in[4];
    const float* b1      = (const float*)d_in[5];
    const float* w_rel   = (const float*)d_in[6];
    const float* w_root  = (const float*)d_in[7];
    const float* b       = (const float*)d_in[8];
    const float* w_out   = (const float*)d_in[9];
    const float* b_out   = (const float*)d_in[10];
    float* out = (float*)d_out;

    const int* src = ei;
    const int* dst = ei + EE;

    float *bufA, *bufB, *agg, *pooled, *cnt;
    int *deg, *pos, *rowptr, *csr_src;
    cudaGetSymbolAddress((void**)&bufA,   g_bufA);
    cudaGetSymbolAddress((void**)&bufB,   g_bufB);
    cudaGetSymbolAddress((void**)&agg,    g_agg);
    cudaGetSymbolAddress((void**)&pooled, g_pooled);
    cudaGetSymbolAddress((void**)&cnt,    g_cnt);
    cudaGetSymbolAddress((void**)&deg,    g_deg);
    cudaGetSymbolAddress((void**)&pos,    g_pos);
    cudaGetSymbolAddress((void**)&rowptr, g_rowptr);
    cudaGetSymbolAddress((void**)&csr_src, g_csr_src);

    // ---- CSR build ----
    zero_kernel<<<(NN + 255) / 256, 256>>>((float*)deg, NN);
    hist_kernel<<<(EE + 255) / 256, 256>>>(dst, deg);
    scan_kernel<<<1, 1024>>>(deg, rowptr, pos);
    fill_kernel<<<(EE + 255) / 256, 256>>>(src, dst, pos, csr_src);

    // ---- layer 1 (F_IN=3) ----
    zero_kernel<<<(NN * 3 + 255) / 256, 256>>>(agg, NN * 3);
    scatter3_kernel<<<(EE + 255) / 256, 256>>>(x, src, dst, agg);
    layer1_kernel<<<(NN + 15) / 16, 256>>>(x, agg, w_rel1, w_root1, b1, bufA);

    // ---- layers 2..7 ----
    float* cur = bufA;
    float* nxt = bufB;
    dim3 ggrid((NN + 127) / 128, HH / 128);
    const int gthreads = 256;
    const int gblocks  = (NN * 2 * 32 + gthreads - 1) / gthreads;
    for (int l = 0; l < 6; ++l) {
        gather_kernel<<<gblocks, gthreads>>>(cur, rowptr, csr_src, agg);
        gemm_dual_relu<<<ggrid, 256>>>(agg, cur,
                                       w_rel  + (size_t)l * HH * HH,
                                       w_root + (size_t)l * HH * HH,
                                       b + (size_t)l * HH, nxt);
        float* t = cur; cur = nxt; nxt = t;
    }

    // ---- pool + head ----
    zero_kernel<<<(GG * HH + 255) / 256, 256>>>(pooled, GG * HH);
    zero_kernel<<<1, 64>>>(cnt, GG);
    pool_kernel<<<(NN * 64 + 255) / 256, 256>>>(cur, batch, pooled, cnt);
    head_kernel<<<GG, 256>>>(pooled, cnt, w_out, b_out, out);
}

// round 4
// speedup vs baseline: 2.1065x; 1.6425x over previous
#include <cuda_runtime.h>
#include <cuda_bf16.h>

#define NN   50000
#define EE   800000
#define HH   256
#define GG   64
#define OUTD 24
#define KP   40   // padded K extent (bf16 elems) for conflict-free smem

// Scratch (allocation-free rule: __device__ globals)
__device__ float g_bufA[NN * HH];
__device__ float g_bufB[NN * HH];
__device__ float g_agg [NN * HH];
__device__ float g_pooled[GG * HH];
__device__ float g_cnt[GG];
__device__ int   g_deg[NN];
__device__ int   g_pos[NN];
__device__ int   g_rowptr[NN + 1];
__device__ int   g_csr_src[EE];
// transposed bf16 hi/lo weights: [12][256n][256k]; mats 0..5 = w_rel, 6..11 = w_root
__device__ __nv_bfloat16 g_whi[12 * HH * HH];
__device__ __nv_bfloat16 g_wlo[12 * HH * HH];

typedef unsigned int u32;

__device__ __forceinline__ void atomAdd4(float* a, float4 v) {
    asm volatile("red.global.add.v4.f32 [%0], {%1,%2,%3,%4};"
                 :: "l"(a), "f"(v.x), "f"(v.y), "f"(v.z), "f"(v.w) : "memory");
}

__device__ __forceinline__ void mma_bf16(float* c, const u32* a, const u32* b) {
    asm volatile("mma.sync.aligned.m16n8k16.row.col.f32.bf16.bf16.f32 "
                 "{%0,%1,%2,%3}, {%4,%5,%6,%7}, {%8,%9}, {%0,%1,%2,%3};"
                 : "+f"(c[0]), "+f"(c[1]), "+f"(c[2]), "+f"(c[3])
                 : "r"(a[0]), "r"(a[1]), "r"(a[2]), "r"(a[3]),
                   "r"(b[0]), "r"(b[1]));
}

__global__ void zero_kernel(float* __restrict__ p, int n) {
    int i = blockIdx.x * blockDim.x + threadIdx.x;
    if (i < n) p[i] = 0.f;
}

// ---------------- weight convert + transpose (once per launch) ----------------
// in: w_rel[6][256k][256n], w_root[6][256k][256n]  ->  out [12][256n][256k] hi/lo bf16
__global__ void wconv_kernel(const float* __restrict__ w_rel,
                             const float* __restrict__ w_root) {
    __shared__ float s[32][33];
    int bid = blockIdx.x;            // 12 mats * 64 tiles
    int mat = bid >> 6;
    int ti  = bid & 63;
    int tk = (ti >> 3) * 32;
    int tn = (ti & 7) * 32;
    const float* in = (mat < 6) ? (w_rel + (size_t)mat * HH * HH)
                                : (w_root + (size_t)(mat - 6) * HH * HH);
    int t = threadIdx.x;
    int col = t & 31, r0 = t >> 5;
    #pragma unroll
    for (int j = 0; j < 4; ++j) {
        int row = r0 + j * 8;
        s[row][col] = in[(size_t)(tk + row) * HH + tn + col];
    }
    __syncthreads();
    __nv_bfloat16* whi = g_whi + (size_t)mat * HH * HH;
    __nv_bfloat16* wlo = g_wlo + (size_t)mat * HH * HH;
    #pragma unroll
    for (int j = 0; j < 4; ++j) {
        int row = r0 + j * 8;              // n-local
        float x = s[col][row];             // (k=tk+col, n=tn+row)
        __nv_bfloat16 hi = __float2bfloat16(x);
        __nv_bfloat16 lo = __float2bfloat16(x - __bfloat162float(hi));
        size_t o = (size_t)(tn + row) * HH + tk + col;
        whi[o] = hi;
        wlo[o] = lo;
    }
}

// ---------------- CSR build ----------------
__global__ void hist_kernel(const int* __restrict__ dst, int* __restrict__ deg) {
    int e = blockIdx.x * blockDim.x + threadIdx.x;
    if (e < EE) atomicAdd(&deg[dst[e]], 1);
}

__global__ void scan_kernel(const int* __restrict__ deg,
                            int* __restrict__ rowptr,
                            int* __restrict__ pos) {
    const int T = 1024;
    const int CH = (NN + T - 1) / T;
    __shared__ int wsum[32];
    int t = threadIdx.x;
    int start = t * CH;
    int end   = min(start + CH, NN);
    int s = 0;
    for (int i = start; i < end; ++i) s += deg[i];
    int lane = t & 31, wid = t >> 5;
    int v = s;
    #pragma unroll
    for (int o = 1; o < 32; o <<= 1) {
        int u = __shfl_up_sync(0xffffffff, v, o);
        if (lane >= o) v += u;
    }
    if (lane == 31) wsum[wid] = v;
    __syncthreads();
    if (wid == 0) {
        int w = wsum[lane];
        #pragma unroll
        for (int o = 1; o < 32; o <<= 1) {
            int u = __shfl_up_sync(0xffffffff, w, o);
            if (lane >= o) w += u;
        }
        wsum[lane] = w;
    }
    __syncthreads();
    int base = v - s + (wid ? wsum[wid - 1] : 0);
    for (int i = start; i < end; ++i) {
        rowptr[i] = base;
        pos[i]    = base;
        base += deg[i];
    }
    if (t == 0) rowptr[NN] = EE;
}

__global__ void fill_kernel(const int* __restrict__ src,
                            const int* __restrict__ dst,
                            int* __restrict__ pos,
                            int* __restrict__ csr_src) {
    int e = blockIdx.x * blockDim.x + threadIdx.x;
    if (e >= EE) return;
    int p = atomicAdd(&pos[dst[e]], 1);
    csr_src[p] = src[e];
}

// ---------------- layer 1 (F_IN = 3) ----------------
__global__ void scatter3_kernel(const float* __restrict__ x,
                                const int* __restrict__ src,
                                const int* __restrict__ dst,
                                float* __restrict__ agg3) {
    int e = blockIdx.x * blockDim.x + threadIdx.x;
    if (e >= EE) return;
    int s = src[e], d = dst[e];
    atomicAdd(&agg3[d * 3 + 0], x[s * 3 + 0]);
    atomicAdd(&agg3[d * 3 + 1], x[s * 3 + 1]);
    atomicAdd(&agg3[d * 3 + 2], x[s * 3 + 2]);
}

__global__ void layer1_kernel(const float* __restrict__ x,
                              const float* __restrict__ agg3,
                              const float* __restrict__ wr,
                              const float* __restrict__ wo,
                              const float* __restrict__ bias,
                              float* __restrict__ out) {
    __shared__ float swr[3 * HH];
    __shared__ float swo[3 * HH];
    int tid = threadIdx.x;
    for (int i = tid; i < 3 * HH; i += 256) { swr[i] = wr[i]; swo[i] = wo[i]; }
    __syncthreads();
    float bb = bias[tid];
    int base = blockIdx.x * 16;
    for (int nn = 0; nn < 16; ++nn) {
        int node = base + nn;
        if (node >= NN) break;
        float a0 = agg3[node * 3 + 0], a1 = agg3[node * 3 + 1], a2 = agg3[node * 3 + 2];
        float x0 = x[node * 3 + 0],    x1 = x[node * 3 + 1],    x2 = x[node * 3 + 2];
        float v = a0 * swr[0 * HH + tid] + a1 * swr[1 * HH + tid] + a2 * swr[2 * HH + tid]
                + x0 * swo[0 * HH + tid] + x1 * swo[1 * HH + tid] + x2 * swo[2 * HH + tid]
                + bb;
        out[node * HH + tid] = fmaxf(v, 0.f);
    }
}

// ---------------- CSR gather aggregation ----------------
__global__ void gather_kernel(const float* __restrict__ h,
                              const int* __restrict__ rowptr,
                              const int* __restrict__ csr_src,
                              float* __restrict__ agg) {
    int w = (blockIdx.x * blockDim.x + threadIdx.x) >> 5;
    int lane = threadIdx.x & 31;
    int node = w >> 1;
    if (node >= NN) return;
    int col = ((w & 1) << 7) + (lane << 2);
    int e0 = rowptr[node];
    int e1 = rowptr[node + 1];
    float4 acc = make_float4(0.f, 0.f, 0.f, 0.f);
    for (int e = e0; e < e1; ++e) {
        int s = __ldg(&csr_src[e]);
        float4 v = *(const float4*)&h[(size_t)s * HH + col];
        acc.x += v.x; acc.y += v.y; acc.z += v.z; acc.w += v.w;
    }
    *(float4*)&agg[(size_t)node * HH + col] = acc;
}

// ---------------- tensor-core dual GEMM (bf16 hi/lo split) ----------------
// out = relu(A1 @ W1 + A2 @ W2 + bias)
// W given pre-transposed [n][k] as bf16 hi/lo. Block tile 128x128, 8 warps,
// warp tile 32x64, K-tile 32, single-stage smem with register prefetch.
__global__ __launch_bounds__(256, 2)
void gemm_mma(const float* __restrict__ A1,
              const float* __restrict__ A2,
              const __nv_bfloat16* __restrict__ W1h,
              const __nv_bfloat16* __restrict__ W1l,
              const __nv_bfloat16* __restrict__ W2h,
              const __nv_bfloat16* __restrict__ W2l,
              const float* __restrict__ bias,
              float* __restrict__ out) {
    __shared__ __nv_bfloat16 Ah[128][KP], Al[128][KP];
    __shared__ __nv_bfloat16 Bh[128][KP], Bl[128][KP];

    int tid = threadIdx.x;
    int lane = tid & 31;
    int warp = tid >> 5;
    int wm = (warp >> 1) * 32;     // warp row base in tile
    int wn = (warp & 1) * 64;      // warp col base in tile
    int m0 = blockIdx.x * 128;
    int n0 = blockIdx.y * 128;

    float acc[2][8][4];
    #pragma unroll
    for (int i = 0; i < 2; i++)
        #pragma unroll
        for (int j = 0; j < 8; j++)
            #pragma unroll
            for (int q = 0; q < 4; q++) acc[i][j][q] = 0.f;

    // prefetch registers
    float4 pa[4];
    float4 pbh[2], pbl[2];

    // A loader: 128 rows x 32 k fp32; tid+i*256 -> row=idx>>3, kc=(idx&7)*4
    // B loader: 128 n-rows x 32 k bf16; tid+i*256 -> row=idx>>2, kc=(idx&3)*8
    auto loadA = [&](const float* A, int kt) {
        #pragma unroll
        for (int i = 0; i < 4; ++i) {
            int idx = tid + i * 256;
            int r = idx >> 3, c = (idx & 7) << 2;
            int gr = m0 + r; if (gr >= NN) gr = NN - 1;
            pa[i] = *(const float4*)&A[(size_t)gr * HH + kt * 32 + c];
        }
    };
    auto loadB = [&](const __nv_bfloat16* Wh, const __nv_bfloat16* Wl, int kt) {
        #pragma unroll
        for (int i = 0; i < 2; ++i) {
            int idx = tid + i * 256;
            int r = idx >> 2, c = (idx & 3) << 3;
            size_t o = (size_t)(n0 + r) * HH + kt * 32 + c;
            pbh[i] = *(const float4*)&Wh[o];
            pbl[i] = *(const float4*)&Wl[o];
        }
    };
    auto storeTiles = [&]() {
        #pragma unroll
        for (int i = 0; i < 4; ++i) {
            int idx = tid + i * 256;
            int r = idx >> 3, c = (idx & 7) << 2;
            const float* f = (const float*)&pa[i];
            #pragma unroll
            for (int j = 0; j < 2; ++j) {
                float x0 = f[2 * j], x1 = f[2 * j + 1];
                __nv_bfloat16 h0 = __float2bfloat16(x0);
                __nv_bfloat16 h1 = __float2bfloat16(x1);
                __nv_bfloat162 hh; hh.x = h0; hh.y = h1;
                __nv_bfloat162 ll;
                ll.x = __float2bfloat16(x0 - __bfloat162float(h0));
                ll.y = __float2bfloat16(x1 - __bfloat162float(h1));
                *(__nv_bfloat162*)&Ah[r][c + 2 * j] = hh;
                *(__nv_bfloat162*)&Al[r][c + 2 * j] = ll;
            }
        }
        #pragma unroll
        for (int i = 0; i < 2; ++i) {
            int idx = tid + i * 256;
            int r = idx >> 2, c = (idx & 3) << 3;
            const u32* ph = (const u32*)&pbh[i];
            const u32* pl = (const u32*)&pbl[i];
            #pragma unroll
            for (int j = 0; j < 4; ++j) {
                *(u32*)&Bh[r][c + 2 * j] = ph[j];
                *(u32*)&Bl[r][c + 2 * j] = pl[j];
            }
        }
    };

    loadA(A1, 0);
    loadB(W1h, W1l, 0);
    storeTiles();
    __syncthreads();

    for (int it = 0; it < 16; ++it) {
        int nxt = it + 1;
        if (nxt < 16) {
            const float* A = (nxt >= 8) ? A2 : A1;
            loadA(A, nxt & 7);
            if (nxt >= 8) loadB(W2h, W2l, nxt & 7);
            else          loadB(W1h, W1l, nxt & 7);
        }
        // compute on current tile
        #pragma unroll
        for (int k16 = 0; k16 < 32; k16 += 16) {
            u32 ah[2][4], al[2][4];
            int kk = k16 + (lane & 3) * 2;
            #pragma unroll
            for (int am = 0; am < 2; ++am) {
                int r0 = wm + am * 16 + (lane >> 2);
                ah[am][0] = *(u32*)&Ah[r0][kk];
                ah[am][1] = *(u32*)&Ah[r0 + 8][kk];
                ah[am][2] = *(u32*)&Ah[r0][kk + 8];
                ah[am][3] = *(u32*)&Ah[r0 + 8][kk + 8];
                al[am][0] = *(u32*)&Al[r0][kk];
                al[am][1] = *(u32*)&Al[r0 + 8][kk];
                al[am][2] = *(u32*)&Al[r0][kk + 8];
                al[am][3] = *(u32*)&Al[r0 + 8][kk + 8];
            }
            #pragma unroll
            for (int na = 0; na < 8; ++na) {
                int n = wn + na * 8 + (lane >> 2);
                u32 bh[2], bl[2];
                bh[0] = *(u32*)&Bh[n][kk];
                bh[1] = *(u32*)&Bh[n][kk + 8];
                bl[0] = *(u32*)&Bl[n][kk];
                bl[1] = *(u32*)&Bl[n][kk + 8];
                #pragma unroll
                for (int am = 0; am < 2; ++am) {
                    mma_bf16(acc[am][na], ah[am], bh);   // hi*hi
                    mma_bf16(acc[am][na], ah[am], bl);   // hi*lo
                    mma_bf16(acc[am][na], al[am], bh);   // lo*hi
                }
            }
        }
        __syncthreads();
        if (nxt < 16) {
            storeTiles();
            __syncthreads();
        }
    }

    // epilogue: bias + relu, fp32 stores
    #pragma unroll
    for (int am = 0; am < 2; ++am) {
        int gr0 = m0 + wm + am * 16 + (lane >> 2);
        int gr1 = gr0 + 8;
        #pragma unroll
        for (int na = 0; na < 8; ++na) {
            int c = n0 + wn + na * 8 + (lane & 3) * 2;
            float b0 = __ldg(&bias[c]);
            float b1 = __ldg(&bias[c + 1]);
            if (gr0 < NN) {
                float2 v;
                v.x = fmaxf(acc[am][na][0] + b0, 0.f);
                v.y = fmaxf(acc[am][na][1] + b1, 0.f);
                *(float2*)&out[(size_t)gr0 * HH + c] = v;
            }
            if (gr1 < NN) {
                float2 v;
                v.x = fmaxf(acc[am][na][2] + b0, 0.f);
                v.y = fmaxf(acc[am][na][3] + b1, 0.f);
                *(float2*)&out[(size_t)gr1 * HH + c] = v;
            }
        }
    }
}

// ---------------- pooling + head ----------------
__global__ void pool_kernel(const float* __restrict__ h,
                            const int* __restrict__ batch,
                            float* __restrict__ pooled,
                            float* __restrict__ cnt) {
    int idx = blockIdx.x * blockDim.x + threadIdx.x;
    if (idx >= NN * 64) return;
    int i = idx >> 6;
    int q = (idx & 63) << 2;
    int b = batch[i];
    float4 v = *(const float4*)&h[(size_t)i * HH + q];
    atomAdd4(&pooled[(size_t)b * HH + q], v);
    if ((idx & 63) == 0) atomicAdd(&cnt[b], 1.f);
}

__global__ void head_kernel(const float* __restrict__ pooled,
                            const float* __restrict__ cnt,
                            const float* __restrict__ w_out,
                            const float* __restrict__ b_out,
                            float* __restrict__ out) {
    __shared__ float row[HH];
    int g = blockIdx.x, t = threadIdx.x;
    float c = fmaxf(cnt[g], 1.f);
    row[t] = pooled[g * HH + t] / c;
    __syncthreads();
    if (t < OUTD) {
        float s = b_out[t];
        #pragma unroll 8
        for (int k = 0; k < HH; k++) s += row[k] * w_out[k * OUTD + t];
        out[g * OUTD + t] = s;
    }
}

extern "C" void kernel_launch(void* const* d_in, const int* in_sizes, int n_in,
                              void* d_out, int out_size) {
    const float* x       = (const float*)d_in[0];
    const int*   ei      = (const int*)  d_in[1];
    const int*   batch   = (const int*)  d_in[2];
    const float* w_rel1  = (const float*)d_in[3];
    const float* w_root1 = (const float*)d_in[4];
    const float* b1      = (const float*)d_in[5];
    const float* w_rel   = (const float*)d_in[6];
    const float* w_root  = (const float*)d_in[7];
    const float* b       = (const float*)d_in[8];
    const float* w_out   = (const float*)d_in[9];
    const float* b_out   = (const float*)d_in[10];
    float* out = (float*)d_out;

    const int* src = ei;
    const int* dst = ei + EE;

    float *bufA, *bufB, *agg, *pooled, *cnt;
    int *deg, *pos, *rowptr, *csr_src;
    __nv_bfloat16 *whi, *wlo;
    cudaGetSymbolAddress((void**)&bufA,   g_bufA);
    cudaGetSymbolAddress((void**)&bufB,   g_bufB);
    cudaGetSymbolAddress((void**)&agg,    g_agg);
    cudaGetSymbolAddress((void**)&pooled, g_pooled);
    cudaGetSymbolAddress((void**)&cnt,    g_cnt);
    cudaGetSymbolAddress((void**)&deg,    g_deg);
    cudaGetSymbolAddress((void**)&pos,    g_pos);
    cudaGetSymbolAddress((void**)&rowptr, g_rowptr);
    cudaGetSymbolAddress((void**)&csr_src, g_csr_src);
    cudaGetSymbolAddress((void**)&whi,    g_whi);
    cudaGetSymbolAddress((void**)&wlo,    g_wlo);

    // ---- weight convert (+transpose) & CSR build ----
    wconv_kernel<<<12 * 64, 256>>>(w_rel, w_root);
    zero_kernel<<<(NN + 255) / 256, 256>>>((float*)deg, NN);
    hist_kernel<<<(EE + 255) / 256, 256>>>(dst, deg);
    scan_kernel<<<1, 1024>>>(deg, rowptr, pos);
    fill_kernel<<<(EE + 255) / 256, 256>>>(src, dst, pos, csr_src);

    // ---- layer 1 (F_IN=3) ----
    zero_kernel<<<(NN * 3 + 255) / 256, 256>>>(agg, NN * 3);
    scatter3_kernel<<<(EE + 255) / 256, 256>>>(x, src, dst, agg);
    layer1_kernel<<<(NN + 15) / 16, 256>>>(x, agg, w_rel1, w_root1, b1, bufA);

    // ---- layers 2..7 ----
    float* cur = bufA;
    float* nxt = bufB;
    dim3 ggrid((NN + 127) / 128, HH / 128);
    const int gthreads = 256;
    const int gblocks  = (NN * 2 * 32 + gthreads - 1) / gthreads;
    for (int l = 0; l < 6; ++l) {
        gather_kernel<<<gblocks, gthreads>>>(cur, rowptr, csr_src, agg);
        gemm_mma<<<ggrid, 256>>>(agg, cur,
                                 whi + (size_t)l * HH * HH,
                                 wlo + (size_t)l * HH * HH,
                                 whi + (size_t)(6 + l) * HH * HH,
                                 wlo + (size_t)(6 + l) * HH * HH,
                                 b + (size_t)l * HH, nxt);
        float* t = cur; cur = nxt; nxt = t;
    }

    // ---- pool + head ----
    zero_kernel<<<(GG * HH + 255) / 256, 256>>>(pooled, GG * HH);
    zero_kernel<<<1, 64>>>(cnt, GG);
    pool_kernel<<<(NN * 64 + 255) / 256, 256>>>(cur, batch, pooled, cnt);
    head_kernel<<<GG, 256>>>(pooled, cnt, w_out, b_out, out);
}